// round 3
// baseline (speedup 1.0000x reference)
#include <cuda_runtime.h>
#include <math.h>

#define N_TOT 512
#define D_DIM 512
#define GRID  129          // 128 gemm blocks + 1 sort block
#define NTHR  128

__device__ float  g_LO[N_TOT * N_TOT];   // lo = -dist/2, natural order
__device__ float  g_ys[N_TOT];           // labels sorted ascending
__device__ int    g_perm[N_TOT];         // g_ys[m] = y[g_perm[m]]
__device__ double g_acc;                 // zero-initialized; self-resets each replay
__device__ unsigned g_cnt;               // monotonic grid-barrier counter
__device__ unsigned g_done;              // monotonic completion counter

__device__ __forceinline__ const float* frow(const float* wt, const float* mt, int r) {
    return (r < 256) ? (wt + r * D_DIM) : (mt + (r - 256) * D_DIM);
}
__device__ __forceinline__ float lab(const float* lw, const float* lm, int r) {
    return (r < 256) ? lw[r] : lm[r - 256];
}

#define BM 64
#define BN 32
#define BK 32
#define NK_ITERS (D_DIM / BK)

__global__ void __launch_bounds__(NTHR)
fused_kernel(const float* __restrict__ wt, const float* __restrict__ mt,
             const float* __restrict__ lw, const float* __restrict__ lm,
             float* __restrict__ out) {
    __shared__ union {
        struct {
            float A[2][BK][BM + 4];
            float B[2][BK][BN + 4];
            float NA[BM];
            float NB[BN];
        } g;
        struct {
            float Y[N_TOT];      // sorted labels
            float Lab[N_TOT];    // natural-order labels
            int   Perm[N_TOT];
            float LOr[N_TOT];    // current row of lo
            float P[N_TOT + 1];  // exclusive prefix of sorted e
            float W[16];
        } l;
    } sm;

    const int t   = threadIdx.x;
    const int bid = blockIdx.x;
    const int lane = t & 31, w = t >> 5;

    // ===================== Phase 1 =====================
    if (bid < 128) {
        // ---- GEMM tile: lo[i,j] = -0.5*sqrt(max(ni+nj-2*F_i.F_j, 0)) ----
        const int i0 = (bid >> 4) * BM;
        const int j0 = (bid & 15) * BN;
        const int tx = t & 7;
        const int ty = t >> 3;

        float acc[4][4] = {};
        float na[4] = {}, nb[4] = {};

        int arow[4], akq[4], brow[2], bkq[2];
        #pragma unroll
        for (int r = 0; r < 4; r++) { int fid = t + r * 128; arow[r] = fid >> 3; akq[r] = fid & 7; }
        #pragma unroll
        for (int r = 0; r < 2; r++) { int fid = t + r * 128; brow[r] = fid >> 3; bkq[r] = fid & 7; }

        float4 pa[4], pb[2];
        #pragma unroll
        for (int r = 0; r < 4; r++)
            pa[r] = ((const float4*)(frow(wt, mt, i0 + arow[r])))[akq[r]];
        #pragma unroll
        for (int r = 0; r < 2; r++)
            pb[r] = ((const float4*)(frow(wt, mt, j0 + brow[r])))[bkq[r]];

        #pragma unroll
        for (int r = 0; r < 4; r++) {
            sm.g.A[0][akq[r]*4+0][arow[r]] = pa[r].x; sm.g.A[0][akq[r]*4+1][arow[r]] = pa[r].y;
            sm.g.A[0][akq[r]*4+2][arow[r]] = pa[r].z; sm.g.A[0][akq[r]*4+3][arow[r]] = pa[r].w;
        }
        #pragma unroll
        for (int r = 0; r < 2; r++) {
            sm.g.B[0][bkq[r]*4+0][brow[r]] = pb[r].x; sm.g.B[0][bkq[r]*4+1][brow[r]] = pb[r].y;
            sm.g.B[0][bkq[r]*4+2][brow[r]] = pb[r].z; sm.g.B[0][bkq[r]*4+3][brow[r]] = pb[r].w;
        }
        __syncthreads();

        for (int n = 0; n < NK_ITERS; n++) {
            int cur = n & 1;
            if (n + 1 < NK_ITERS) {
                int k0 = (n + 1) * BK;
                #pragma unroll
                for (int r = 0; r < 4; r++)
                    pa[r] = ((const float4*)(frow(wt, mt, i0 + arow[r]) + k0))[akq[r]];
                #pragma unroll
                for (int r = 0; r < 2; r++)
                    pb[r] = ((const float4*)(frow(wt, mt, j0 + brow[r]) + k0))[bkq[r]];
            }
            #pragma unroll 8
            for (int kk = 0; kk < BK; kk++) {
                float4 a4 = *(const float4*)&sm.g.A[cur][kk][ty * 4];
                float4 b4 = *(const float4*)&sm.g.B[cur][kk][tx * 4];
                float a[4] = {a4.x, a4.y, a4.z, a4.w};
                float b[4] = {b4.x, b4.y, b4.z, b4.w};
                if (tx == 0) {
                    #pragma unroll
                    for (int u = 0; u < 4; u++) na[u] = fmaf(a[u], a[u], na[u]);
                }
                if (ty == 0) {
                    #pragma unroll
                    for (int v = 0; v < 4; v++) nb[v] = fmaf(b[v], b[v], nb[v]);
                }
                #pragma unroll
                for (int u = 0; u < 4; u++)
                    #pragma unroll
                    for (int v = 0; v < 4; v++)
                        acc[u][v] = fmaf(a[u], b[v], acc[u][v]);
            }
            if (n + 1 < NK_ITERS) {
                int nxt = cur ^ 1;
                #pragma unroll
                for (int r = 0; r < 4; r++) {
                    sm.g.A[nxt][akq[r]*4+0][arow[r]] = pa[r].x; sm.g.A[nxt][akq[r]*4+1][arow[r]] = pa[r].y;
                    sm.g.A[nxt][akq[r]*4+2][arow[r]] = pa[r].z; sm.g.A[nxt][akq[r]*4+3][arow[r]] = pa[r].w;
                }
                #pragma unroll
                for (int r = 0; r < 2; r++) {
                    sm.g.B[nxt][bkq[r]*4+0][brow[r]] = pb[r].x; sm.g.B[nxt][bkq[r]*4+1][brow[r]] = pb[r].y;
                    sm.g.B[nxt][bkq[r]*4+2][brow[r]] = pb[r].z; sm.g.B[nxt][bkq[r]*4+3][brow[r]] = pb[r].w;
                }
                __syncthreads();
            }
        }

        if (tx == 0) {
            #pragma unroll
            for (int u = 0; u < 4; u++) sm.g.NA[ty * 4 + u] = na[u];
        }
        if (ty == 0) {
            #pragma unroll
            for (int v = 0; v < 4; v++) sm.g.NB[tx * 4 + v] = nb[v];
        }
        __syncthreads();

        #pragma unroll
        for (int u = 0; u < 4; u++) {
            int i = i0 + ty * 4 + u;
            float ni = sm.g.NA[ty * 4 + u];
            float4 o;
            float* op = &o.x;
            #pragma unroll
            for (int v = 0; v < 4; v++) {
                float sq = ni + sm.g.NB[tx * 4 + v] - 2.f * acc[u][v];
                op[v] = -0.5f * sqrtf(fmaxf(sq, 0.f));   // temperature = 2.0
            }
            *(float4*)&g_LO[i * N_TOT + j0 + tx * 4] = o;
        }
    } else {
        // ---- Rank-based sort of the 512 labels (runs concurrently with GEMM) ----
        for (int m = t; m < N_TOT; m += NTHR) sm.l.Lab[m] = lab(lw, lm, m);
        __syncthreads();
        const float4* L4 = (const float4*)sm.l.Lab;
        #pragma unroll
        for (int r = 0; r < 4; r++) {
            int k = t + r * NTHR;
            float yk = sm.l.Lab[k];
            int rank = 0;
            for (int j4 = 0; j4 < N_TOT / 4; j4++) {
                float4 v = L4[j4];
                int j = j4 * 4;
                rank += (v.x < yk) || (v.x == yk && (j + 0) < k);
                rank += (v.y < yk) || (v.y == yk && (j + 1) < k);
                rank += (v.z < yk) || (v.z == yk && (j + 2) < k);
                rank += (v.w < yk) || (v.w == yk && (j + 3) < k);
            }
            g_ys[rank]   = yk;
            g_perm[rank] = k;
        }
    }

    // ===================== Grid barrier (monotonic, replay-safe) =====================
    __syncthreads();
    if (t == 0) {
        __threadfence();
        unsigned ticket = atomicAdd(&g_cnt, 1u);
        unsigned target = (ticket / GRID + 1u) * GRID;
        while (atomicAdd(&g_cnt, 0u) < target) { }
        __threadfence();
    }
    __syncthreads();

    // ===================== Phase 2: loss rows =====================
    for (int m = t; m < N_TOT; m += NTHR) {
        sm.l.Y[m]    = g_ys[m];
        sm.l.Lab[m]  = lab(lw, lm, m);
        sm.l.Perm[m] = g_perm[m];
    }
    __syncthreads();

    float local = 0.f;
    for (int row = bid; row < N_TOT; row += GRID) {
        __syncthreads();   // protect LOr/P reuse across iterations
        ((float4*)sm.l.LOr)[t] = ((const float4*)(g_LO + row * N_TOT))[t];
        __syncthreads();

        float yi = sm.l.Lab[row];

        // e in sorted order for positions m = 4t..4t+3 (diagonal -> 0)
        float e0, e1, e2, e3;
        {
            int m0 = 4 * t;
            int p0 = sm.l.Perm[m0+0], p1 = sm.l.Perm[m0+1];
            int p2 = sm.l.Perm[m0+2], p3 = sm.l.Perm[m0+3];
            e0 = (p0 == row) ? 0.f : expf(sm.l.LOr[p0]);
            e1 = (p1 == row) ? 0.f : expf(sm.l.LOr[p1]);
            e2 = (p2 == row) ? 0.f : expf(sm.l.LOr[p2]);
            e3 = (p3 == row) ? 0.f : expf(sm.l.LOr[p3]);
        }
        float s0 = e0, s1 = s0 + e1, s2 = s1 + e2, s3 = s2 + e3;

        // warp inclusive scan of thread totals
        float ws = s3;
        #pragma unroll
        for (int o = 1; o < 32; o <<= 1) {
            float nv = __shfl_up_sync(0xffffffffu, ws, o);
            if (lane >= o) ws += nv;
        }
        if (lane == 31) sm.l.W[w] = ws;
        __syncthreads();
        if (t == 0) {
            float a = sm.l.W[0], b = sm.l.W[1], c = sm.l.W[2];
            sm.l.W[4] = 0.f; sm.l.W[5] = a; sm.l.W[6] = a + b; sm.l.W[7] = a + b + c;
        }
        __syncthreads();
        float base = sm.l.W[4 + w] + (ws - s3);   // exclusive prefix at m=4t
        int m0 = 4 * t;
        sm.l.P[m0 + 0] = base;
        sm.l.P[m0 + 1] = base + s0;
        sm.l.P[m0 + 2] = base + s1;
        sm.l.P[m0 + 3] = base + s2;
        if (t == NTHR - 1) sm.l.P[N_TOT] = base + s3;
        __syncthreads();

        float S = sm.l.P[N_TOT];

        // p = first m with Y[m] >= yi (same for all k in this row)
        int plo = 0, phi = N_TOT;
        while (plo < phi) { int mid = (plo + phi) >> 1; if (sm.l.Y[mid] >= yi) phi = mid; else plo = mid + 1; }
        const int p = plo;

        #pragma unroll
        for (int r = 0; r < 4; r++) {
            int k = 4 * t + r;
            if (k == row) continue;
            float yk = sm.l.Lab[k];
            float th = fabsf(yi - yk);
            // a = first m in [0,p) with fabsf(yi - Y[m]) < th
            int lo_ = 0, hi_ = p;
            while (lo_ < hi_) { int mid = (lo_ + hi_) >> 1; if (fabsf(yi - sm.l.Y[mid]) < th) hi_ = mid; else lo_ = mid + 1; }
            int a = lo_;
            // b = first m in [p,n) with fabsf(yi - Y[m]) >= th
            lo_ = p; hi_ = N_TOT;
            while (lo_ < hi_) { int mid = (lo_ + hi_) >> 1; if (fabsf(yi - sm.l.Y[mid]) >= th) hi_ = mid; else lo_ = mid + 1; }
            int b = lo_;
            float denom = sm.l.P[a] + (S - sm.l.P[b]);
            local += sm.l.LOr[k] - logf(denom);
        }
    }

    // ===================== Block reduce + output =====================
    #pragma unroll
    for (int o = 16; o; o >>= 1) local += __shfl_xor_sync(0xffffffffu, local, o);
    __syncthreads();
    if (lane == 0) sm.l.W[w] = local;
    __syncthreads();
    if (t == 0) {
        float bs = sm.l.W[0] + sm.l.W[1] + sm.l.W[2] + sm.l.W[3];
        atomicAdd(&g_acc, (double)bs);
        __threadfence();
        unsigned d = atomicAdd(&g_done, 1u);
        if (d % GRID == GRID - 1u) {
            double total = atomicAdd(&g_acc, 0.0);
            out[0] = (float)(-total / (double)((double)N_TOT * (N_TOT - 1)));
            g_acc = 0.0;     // self-reset for next replay (ordered by kernel boundary)
            __threadfence();
        }
    }
}

extern "C" void kernel_launch(void* const* d_in, const int* in_sizes, int n_in,
                              void* d_out, int out_size) {
    const float* wt = (const float*)d_in[0];
    const float* mt = (const float*)d_in[1];
    const float* lw = (const float*)d_in[2];
    const float* lm = (const float*)d_in[3];
    float* out = (float*)d_out;

    fused_kernel<<<GRID, NTHR>>>(wt, mt, lw, lm, out);
}

// round 4
// speedup vs baseline: 1.3769x; 1.3769x over previous
#include <cuda_runtime.h>
#include <math.h>

#define N_TOT 512
#define D_DIM 512

__device__ float  g_LO[N_TOT * N_TOT];   // lo = -dist/2, natural order
__device__ float  g_ys[N_TOT];           // labels sorted ascending
__device__ int    g_perm[N_TOT];         // g_ys[m] = y[g_perm[m]]
__device__ double g_acc;
__device__ int    g_count;

__device__ __forceinline__ const float* frow(const float* wt, const float* mt, int r) {
    return (r < 256) ? (wt + r * D_DIM) : (mt + (r - 256) * D_DIM);
}
__device__ __forceinline__ float lab(const float* lw, const float* lm, int r) {
    return (r < 256) ? lw[r] : lm[r - 256];
}

// ---------------------------------------------------------------------------
// Kernel 1: 256 GEMM blocks (32x32 tiles of lo = -0.5*sqrt(ni+nj-2*F_i.F_j))
//           + 1 sort block (rank sort of the 512 labels), 128 threads each.
// ---------------------------------------------------------------------------
#define BM 32
#define BN 32
#define BK 32
#define NK_ITERS (D_DIM / BK)
#define G_GRID 257

__global__ void __launch_bounds__(128)
gemm_sort_kernel(const float* __restrict__ wt, const float* __restrict__ mt,
                 const float* __restrict__ lw, const float* __restrict__ lm) {
    __shared__ union {
        struct {
            float A[2][BK][BM + 2];   // stride 34 (float2-aligned)
            float B[2][BK][BN + 4];   // stride 36 (float4-aligned)
            float NA[BM];
            float NB[BN];
        } g;
        float lab_s[N_TOT];
    } sm;

    const int t   = threadIdx.x;
    const int bid = blockIdx.x;

    if (bid < 256) {
        const int i0 = (bid >> 4) * BM;
        const int j0 = (bid & 15) * BN;
        const int tx = t & 7;     // 8 groups of 4 cols
        const int ty = t >> 3;    // 16 groups of 2 rows

        float acc[2][4] = {};
        float na[2] = {}, nb[4] = {};

        // load mapping: tile = 32 rows x 8 float4; 2 float4 per thread
        int arow[2], akq[2];
        #pragma unroll
        for (int r = 0; r < 2; r++) { int fid = t + r * 128; arow[r] = fid >> 3; akq[r] = fid & 7; }

        float4 pa[2], pb[2];
        #pragma unroll
        for (int r = 0; r < 2; r++) {
            pa[r] = ((const float4*)(frow(wt, mt, i0 + arow[r])))[akq[r]];
            pb[r] = ((const float4*)(frow(wt, mt, j0 + arow[r])))[akq[r]];
        }
        #pragma unroll
        for (int r = 0; r < 2; r++) {
            sm.g.A[0][akq[r]*4+0][arow[r]] = pa[r].x; sm.g.A[0][akq[r]*4+1][arow[r]] = pa[r].y;
            sm.g.A[0][akq[r]*4+2][arow[r]] = pa[r].z; sm.g.A[0][akq[r]*4+3][arow[r]] = pa[r].w;
            sm.g.B[0][akq[r]*4+0][arow[r]] = pb[r].x; sm.g.B[0][akq[r]*4+1][arow[r]] = pb[r].y;
            sm.g.B[0][akq[r]*4+2][arow[r]] = pb[r].z; sm.g.B[0][akq[r]*4+3][arow[r]] = pb[r].w;
        }
        __syncthreads();

        for (int n = 0; n < NK_ITERS; n++) {
            int cur = n & 1;
            if (n + 1 < NK_ITERS) {
                int k0 = (n + 1) * BK;
                #pragma unroll
                for (int r = 0; r < 2; r++) {
                    pa[r] = ((const float4*)(frow(wt, mt, i0 + arow[r]) + k0))[akq[r]];
                    pb[r] = ((const float4*)(frow(wt, mt, j0 + arow[r]) + k0))[akq[r]];
                }
            }
            #pragma unroll 8
            for (int kk = 0; kk < BK; kk++) {
                float2 a2 = *(const float2*)&sm.g.A[cur][kk][ty * 2];
                float4 b4 = *(const float4*)&sm.g.B[cur][kk][tx * 4];
                float a[2] = {a2.x, a2.y};
                float b[4] = {b4.x, b4.y, b4.z, b4.w};
                if (tx == 0) {
                    na[0] = fmaf(a[0], a[0], na[0]);
                    na[1] = fmaf(a[1], a[1], na[1]);
                }
                if (ty == 0) {
                    #pragma unroll
                    for (int v = 0; v < 4; v++) nb[v] = fmaf(b[v], b[v], nb[v]);
                }
                #pragma unroll
                for (int u = 0; u < 2; u++)
                    #pragma unroll
                    for (int v = 0; v < 4; v++)
                        acc[u][v] = fmaf(a[u], b[v], acc[u][v]);
            }
            if (n + 1 < NK_ITERS) {
                int nxt = cur ^ 1;
                #pragma unroll
                for (int r = 0; r < 2; r++) {
                    sm.g.A[nxt][akq[r]*4+0][arow[r]] = pa[r].x; sm.g.A[nxt][akq[r]*4+1][arow[r]] = pa[r].y;
                    sm.g.A[nxt][akq[r]*4+2][arow[r]] = pa[r].z; sm.g.A[nxt][akq[r]*4+3][arow[r]] = pa[r].w;
                    sm.g.B[nxt][akq[r]*4+0][arow[r]] = pb[r].x; sm.g.B[nxt][akq[r]*4+1][arow[r]] = pb[r].y;
                    sm.g.B[nxt][akq[r]*4+2][arow[r]] = pb[r].z; sm.g.B[nxt][akq[r]*4+3][arow[r]] = pb[r].w;
                }
                __syncthreads();
            }
        }

        if (tx == 0) { sm.g.NA[ty*2+0] = na[0]; sm.g.NA[ty*2+1] = na[1]; }
        if (ty == 0) {
            #pragma unroll
            for (int v = 0; v < 4; v++) sm.g.NB[tx * 4 + v] = nb[v];
        }
        __syncthreads();

        #pragma unroll
        for (int u = 0; u < 2; u++) {
            int i = i0 + ty * 2 + u;
            float ni = sm.g.NA[ty * 2 + u];
            float4 o;
            float* op = &o.x;
            #pragma unroll
            for (int v = 0; v < 4; v++) {
                float sq = ni + sm.g.NB[tx * 4 + v] - 2.f * acc[u][v];
                op[v] = -0.5f * sqrtf(fmaxf(sq, 0.f));   // temperature = 2.0
            }
            *(float4*)&g_LO[i * N_TOT + j0 + tx * 4] = o;
        }
    } else {
        // ---- Rank sort of the 512 labels; also resets accumulators ----
        if (t == 0) { g_acc = 0.0; g_count = 0; }
        for (int m = t; m < N_TOT; m += 128) sm.lab_s[m] = lab(lw, lm, m);
        __syncthreads();
        const float4* L4 = (const float4*)sm.lab_s;
        #pragma unroll
        for (int r = 0; r < 4; r++) {
            int k = t + r * 128;
            float yk = sm.lab_s[k];
            int rank = 0;
            for (int j4 = 0; j4 < N_TOT / 4; j4++) {
                float4 v = L4[j4];
                int j = j4 * 4;
                rank += (v.x < yk) || (v.x == yk && (j + 0) < k);
                rank += (v.y < yk) || (v.y == yk && (j + 1) < k);
                rank += (v.z < yk) || (v.z == yk && (j + 2) < k);
                rank += (v.w < yk) || (v.w == yk && (j + 3) < k);
            }
            g_ys[rank]   = yk;
            g_perm[rank] = k;
        }
    }
}

// ---------------------------------------------------------------------------
// Kernel 2: per-row loss. Block = row i, thread = positive idx k.
// denom via prefix sums over label-sorted e + binary searches (exact
// predicate fabsf(yi - yj) >= t, monotone on each side of yi).
// ---------------------------------------------------------------------------
__global__ void __launch_bounds__(N_TOT)
loss_kernel(const float* __restrict__ lw, const float* __restrict__ lm,
            float* __restrict__ out) {
    __shared__ float sLO[N_TOT];
    __shared__ float sY[N_TOT];
    __shared__ float sP[N_TOT + 1];
    __shared__ float warpS[16];

    int i = blockIdx.x;
    int k = threadIdx.x;    // 512
    int lane = k & 31, w = k >> 5;

    sLO[k] = g_LO[i * N_TOT + k];
    sY[k]  = g_ys[k];
    int pm = g_perm[k];
    float yi = lab(lw, lm, i);
    float yk = lab(lw, lm, k);
    __syncthreads();

    // e in sorted order, diagonal forced to 0
    float e = (pm == i) ? 0.f : expf(sLO[pm]);

    // exclusive prefix sum of e
    float v = e;
    #pragma unroll
    for (int o = 1; o < 32; o <<= 1) {
        float nvl = __shfl_up_sync(0xffffffffu, v, o);
        if (lane >= o) v += nvl;
    }
    if (lane == 31) warpS[w] = v;
    __syncthreads();
    if (w == 0) {
        float s = (lane < 16) ? warpS[lane] : 0.f;
        #pragma unroll
        for (int o = 1; o < 16; o <<= 1) {
            float nvl = __shfl_up_sync(0xffffffffu, s, o);
            if (lane >= o) s += nvl;
        }
        if (lane < 16) warpS[lane] = s;
    }
    __syncthreads();
    float off = (w > 0) ? warpS[w - 1] : 0.f;
    float S = warpS[15];
    sP[k] = off + v - e;
    if (k == N_TOT - 1) sP[N_TOT] = off + v;
    __syncthreads();

    float t = fabsf(yi - yk);
    int lo_ = 0, hi_ = N_TOT;
    while (lo_ < hi_) { int mid = (lo_ + hi_) >> 1; if (sY[mid] >= yi) hi_ = mid; else lo_ = mid + 1; }
    int p = lo_;
    lo_ = 0; hi_ = p;   // a = first m in [0,p) with fabsf(yi - sY[m]) < t
    while (lo_ < hi_) { int mid = (lo_ + hi_) >> 1; if (fabsf(yi - sY[mid]) < t) hi_ = mid; else lo_ = mid + 1; }
    int a = lo_;
    lo_ = p; hi_ = N_TOT;  // b = first m in [p,n) with fabsf(yi - sY[m]) >= t
    while (lo_ < hi_) { int mid = (lo_ + hi_) >> 1; if (fabsf(yi - sY[mid]) >= t) hi_ = mid; else lo_ = mid + 1; }
    int b = lo_;

    float denom = sP[a] + (S - sP[b]);
    float term = (k == i) ? 0.f : (sLO[k] - logf(denom));

    // block reduce
    #pragma unroll
    for (int o = 16; o; o >>= 1) term += __shfl_xor_sync(0xffffffffu, term, o);
    __syncthreads();
    if (lane == 0) warpS[w] = term;
    __syncthreads();
    if (k == 0) {
        float s = 0.f;
        #pragma unroll
        for (int q = 0; q < 16; q++) s += warpS[q];
        atomicAdd(&g_acc, (double)s);
        __threadfence();
        int done = atomicAdd(&g_count, 1);
        if (done == N_TOT - 1) {
            double total = atomicAdd(&g_acc, 0.0);
            out[0] = (float)(-total / (double)(N_TOT * (N_TOT - 1)));
        }
    }
}

extern "C" void kernel_launch(void* const* d_in, const int* in_sizes, int n_in,
                              void* d_out, int out_size) {
    const float* wt = (const float*)d_in[0];
    const float* mt = (const float*)d_in[1];
    const float* lw = (const float*)d_in[2];
    const float* lm = (const float*)d_in[3];
    float* out = (float*)d_out;

    gemm_sort_kernel<<<G_GRID, 128>>>(wt, mt, lw, lm);
    loss_kernel<<<N_TOT, N_TOT>>>(lw, lm, out);
}

// round 6
// speedup vs baseline: 1.9889x; 1.4444x over previous
#include <cuda_runtime.h>
#include <cuda_bf16.h>
#include <math.h>
#include <stdint.h>

#define N_TOT 512
#define D_DIM 512

__device__ float  g_LO[N_TOT * N_TOT];   // lo = -dist/2, natural order
__device__ float  g_ys[N_TOT];           // labels sorted ascending
__device__ int    g_perm[N_TOT];         // g_ys[m] = y[g_perm[m]]
__device__ double g_acc;
__device__ int    g_count;

__device__ __forceinline__ const float* frow(const float* wt, const float* mt, int r) {
    return (r < 256) ? (wt + r * D_DIM) : (mt + (r - 256) * D_DIM);
}
__device__ __forceinline__ float lab(const float* lw, const float* lm, int r) {
    return (r < 256) ? lw[r] : lm[r - 256];
}

// ===================== warp-MMA helpers (HMMA bf16, compute_80+ PTX) =====================
__device__ __forceinline__ uint32_t smem_u32(const void* p) {
    uint32_t a;
    asm("{ .reg .u64 t; cvta.to.shared.u64 t, %1; cvt.u32.u64 %0, t; }" : "=r"(a) : "l"(p));
    return a;
}
__device__ __forceinline__ void ldsm4(uint32_t* r, uint32_t addr) {
    asm volatile("ldmatrix.sync.aligned.m8n8.x4.shared.b16 {%0,%1,%2,%3}, [%4];"
                 : "=r"(r[0]), "=r"(r[1]), "=r"(r[2]), "=r"(r[3]) : "r"(addr));
}
__device__ __forceinline__ void mma_bf16(float* c, const uint32_t* a, const uint32_t* b) {
    asm volatile("mma.sync.aligned.m16n8k16.row.col.f32.bf16.bf16.f32 "
                 "{%0,%1,%2,%3}, {%4,%5,%6,%7}, {%8,%9}, {%0,%1,%2,%3};"
                 : "+f"(c[0]), "+f"(c[1]), "+f"(c[2]), "+f"(c[3])
                 : "r"(a[0]), "r"(a[1]), "r"(a[2]), "r"(a[3]), "r"(b[0]), "r"(b[1]));
}

// bf16 split of 8 floats: hi = bf16(x), lo = bf16(x - hi)
__device__ __forceinline__ void split8(float4 f0, float4 f1, uint4& hi, uint4& lo) {
    __nv_bfloat162 h0 = __floats2bfloat162_rn(f0.x, f0.y);
    __nv_bfloat162 h1 = __floats2bfloat162_rn(f0.z, f0.w);
    __nv_bfloat162 h2 = __floats2bfloat162_rn(f1.x, f1.y);
    __nv_bfloat162 h3 = __floats2bfloat162_rn(f1.z, f1.w);
    float2 g0 = __bfloat1622float2(h0), g1 = __bfloat1622float2(h1);
    float2 g2 = __bfloat1622float2(h2), g3 = __bfloat1622float2(h3);
    __nv_bfloat162 l0 = __floats2bfloat162_rn(f0.x - g0.x, f0.y - g0.y);
    __nv_bfloat162 l1 = __floats2bfloat162_rn(f0.z - g1.x, f0.w - g1.y);
    __nv_bfloat162 l2 = __floats2bfloat162_rn(f1.x - g2.x, f1.y - g2.y);
    __nv_bfloat162 l3 = __floats2bfloat162_rn(f1.z - g3.x, f1.w - g3.y);
    hi = make_uint4(*(uint32_t*)&h0, *(uint32_t*)&h1, *(uint32_t*)&h2, *(uint32_t*)&h3);
    lo = make_uint4(*(uint32_t*)&l0, *(uint32_t*)&l1, *(uint32_t*)&l2, *(uint32_t*)&l3);
}

#define STRIDE 40          // bf16 elements per SMEM row (32 data + 8 pad -> 80B)
#define BK 32              // fp32 K per chunk
#define NCHUNK (D_DIM / BK)

struct GemmSmem {
    float nA[64];
    float nB[64];
    unsigned short a_hi[2][64 * STRIDE];
    unsigned short a_lo[2][64 * STRIDE];
    unsigned short b_hi[2][64 * STRIDE];
    unsigned short b_lo[2][64 * STRIDE];
};

// ---------------------------------------------------------------------------
// Kernel 1: 64 HMMA GEMM blocks (64x64 tiles of lo) + 1 sort block, 256 thr.
// ---------------------------------------------------------------------------
__global__ void __launch_bounds__(256, 1)
gemm_sort_kernel(const float* __restrict__ wt, const float* __restrict__ mt,
                 const float* __restrict__ lw, const float* __restrict__ lm) {
    __shared__ GemmSmem sm;

    const int t = threadIdx.x;
    const int bid = blockIdx.x;
    const int w = t >> 5, lane = t & 31;

    if (bid < 64) {
        const int i0 = (bid >> 3) * 64;
        const int j0 = (bid & 7) * 64;

        // load mapping: thread owns row (t>>2), 8 cols at (t&3)*8 of each chunk
        const int lrow = t >> 2, lg = t & 3;
        const float* arp = frow(wt, mt, i0 + lrow) + lg * 8;
        const float* brp = frow(wt, mt, j0 + lrow) + lg * 8;
        float na = 0.f, nb = 0.f;

        // warp tile: wm in 0..3 (16 rows), wn in 0..1 (32 cols)
        const int wm = w >> 1, wn = w & 1;

        float c[4][4] = {};   // 4 n-frags x 4 accum regs

        // ldmatrix addresses (element offsets computed in bytes)
        const uint32_t a_hi_base0 = smem_u32(sm.a_hi[0]);
        const uint32_t a_lo_base0 = smem_u32(sm.a_lo[0]);
        const uint32_t b_hi_base0 = smem_u32(sm.b_hi[0]);
        const uint32_t b_lo_base0 = smem_u32(sm.b_lo[0]);
        const uint32_t bufstep = 64 * STRIDE * 2;  // bytes between buffers

        const int a_row = wm * 16 + (lane & 15);
        const uint32_t a_off = (uint32_t)(a_row * (STRIDE * 2) + ((lane >> 4) & 1) * 16);
        const int b_row0 = wn * 32 + (lane & 7) + ((lane >> 4) & 1) * 8;
        const uint32_t b_off0 = (uint32_t)(b_row0 * (STRIDE * 2) + ((lane >> 3) & 1) * 16);
        const uint32_t b_off1 = b_off0 + 16 * (STRIDE * 2);   // +16 n rows

        float4 fa0, fa1, fb0, fb1;

        // ---- prefetch chunk 0 ----
        fa0 = ((const float4*)arp)[0]; fa1 = ((const float4*)arp)[1];
        fb0 = ((const float4*)brp)[0]; fb1 = ((const float4*)brp)[1];

        // ---- store chunk 0 ----
        {
            uint4 hi, lo;
            na += fa0.x*fa0.x + fa0.y*fa0.y + fa0.z*fa0.z + fa0.w*fa0.w
                + fa1.x*fa1.x + fa1.y*fa1.y + fa1.z*fa1.z + fa1.w*fa1.w;
            split8(fa0, fa1, hi, lo);
            *(uint4*)&sm.a_hi[0][lrow * STRIDE + lg * 8] = hi;
            *(uint4*)&sm.a_lo[0][lrow * STRIDE + lg * 8] = lo;
            nb += fb0.x*fb0.x + fb0.y*fb0.y + fb0.z*fb0.z + fb0.w*fb0.w
                + fb1.x*fb1.x + fb1.y*fb1.y + fb1.z*fb1.z + fb1.w*fb1.w;
            split8(fb0, fb1, hi, lo);
            *(uint4*)&sm.b_hi[0][lrow * STRIDE + lg * 8] = hi;
            *(uint4*)&sm.b_lo[0][lrow * STRIDE + lg * 8] = lo;
        }
        __syncthreads();

        for (int cch = 0; cch < NCHUNK; cch++) {
            const int cur = cch & 1;
            if (cch + 1 < NCHUNK) {
                const float* ap = arp + (cch + 1) * BK;
                const float* bp = brp + (cch + 1) * BK;
                fa0 = ((const float4*)ap)[0]; fa1 = ((const float4*)ap)[1];
                fb0 = ((const float4*)bp)[0]; fb1 = ((const float4*)bp)[1];
            }

            // ---- compute on buffer cur: 2 ksteps of 16 ----
            #pragma unroll
            for (int ks = 0; ks < 2; ks++) {
                const uint32_t koff = (uint32_t)(cur * bufstep + ks * 32);
                uint32_t Ah[4], Al[4], Bh0[4], Bl0[4], Bh1[4], Bl1[4];
                ldsm4(Ah, a_hi_base0 + koff + a_off);
                ldsm4(Al, a_lo_base0 + koff + a_off);
                ldsm4(Bh0, b_hi_base0 + koff + b_off0);
                ldsm4(Bl0, b_lo_base0 + koff + b_off0);
                ldsm4(Bh1, b_hi_base0 + koff + b_off1);
                ldsm4(Bl1, b_lo_base0 + koff + b_off1);

                mma_bf16(c[0], Ah, Bh0 + 0);
                mma_bf16(c[1], Ah, Bh0 + 2);
                mma_bf16(c[2], Ah, Bh1 + 0);
                mma_bf16(c[3], Ah, Bh1 + 2);
                mma_bf16(c[0], Ah, Bl0 + 0);
                mma_bf16(c[1], Ah, Bl0 + 2);
                mma_bf16(c[2], Ah, Bl1 + 0);
                mma_bf16(c[3], Ah, Bl1 + 2);
                mma_bf16(c[0], Al, Bh0 + 0);
                mma_bf16(c[1], Al, Bh0 + 2);
                mma_bf16(c[2], Al, Bh1 + 0);
                mma_bf16(c[3], Al, Bh1 + 2);
            }

            if (cch + 1 < NCHUNK) {
                const int nxt = cur ^ 1;
                uint4 hi, lo;
                na += fa0.x*fa0.x + fa0.y*fa0.y + fa0.z*fa0.z + fa0.w*fa0.w
                    + fa1.x*fa1.x + fa1.y*fa1.y + fa1.z*fa1.z + fa1.w*fa1.w;
                split8(fa0, fa1, hi, lo);
                *(uint4*)&sm.a_hi[nxt][lrow * STRIDE + lg * 8] = hi;
                *(uint4*)&sm.a_lo[nxt][lrow * STRIDE + lg * 8] = lo;
                nb += fb0.x*fb0.x + fb0.y*fb0.y + fb0.z*fb0.z + fb0.w*fb0.w
                    + fb1.x*fb1.x + fb1.y*fb1.y + fb1.z*fb1.z + fb1.w*fb1.w;
                split8(fb0, fb1, hi, lo);
                *(uint4*)&sm.b_hi[nxt][lrow * STRIDE + lg * 8] = hi;
                *(uint4*)&sm.b_lo[nxt][lrow * STRIDE + lg * 8] = lo;
                __syncthreads();
            }
        }

        // ---- norms: reduce across the 4 threads sharing a row ----
        na += __shfl_xor_sync(0xffffffffu, na, 1);
        na += __shfl_xor_sync(0xffffffffu, na, 2);
        nb += __shfl_xor_sync(0xffffffffu, nb, 1);
        nb += __shfl_xor_sync(0xffffffffu, nb, 2);
        __syncthreads();   // all compute done before nA/nB overwrite (union-free here, but order anyway)
        if ((t & 3) == 0) { sm.nA[lrow] = na; sm.nB[lrow] = nb; }
        __syncthreads();

        // ---- epilogue ----
        const int r_lo = wm * 16 + (lane >> 2);
        const float ni0 = sm.nA[r_lo];
        const float ni1 = sm.nA[r_lo + 8];
        const int gi0 = i0 + r_lo;
        #pragma unroll
        for (int nf = 0; nf < 4; nf++) {
            const int colL = wn * 32 + nf * 8 + (lane & 3) * 2;
            const float nj0 = sm.nB[colL], nj1 = sm.nB[colL + 1];
            const int gcol = j0 + colL;
            float2 o0, o1;
            float sq;
            sq = fmaf(-2.f, c[nf][0], ni0 + nj0); o0.x = -0.5f * sqrtf(fmaxf(sq, 0.f));
            sq = fmaf(-2.f, c[nf][1], ni0 + nj1); o0.y = -0.5f * sqrtf(fmaxf(sq, 0.f));
            sq = fmaf(-2.f, c[nf][2], ni1 + nj0); o1.x = -0.5f * sqrtf(fmaxf(sq, 0.f));
            sq = fmaf(-2.f, c[nf][3], ni1 + nj1); o1.y = -0.5f * sqrtf(fmaxf(sq, 0.f));
            *(float2*)&g_LO[gi0 * N_TOT + gcol] = o0;
            *(float2*)&g_LO[(gi0 + 8) * N_TOT + gcol] = o1;
        }
    } else {
        // ---- Rank sort of the 512 labels; resets accumulators ----
        if (t == 0) { g_acc = 0.0; g_count = 0; }
        float* ls = (float*)&sm;
        for (int m = t; m < N_TOT; m += 256) ls[m] = lab(lw, lm, m);
        __syncthreads();
        const float4* L4 = (const float4*)ls;
        #pragma unroll
        for (int r = 0; r < 2; r++) {
            int k = t + r * 256;
            float yk = ls[k];
            int rank = 0;
            for (int j4 = 0; j4 < N_TOT / 4; j4++) {
                float4 v = L4[j4];
                int j = j4 * 4;
                rank += (v.x < yk) || (v.x == yk && (j + 0) < k);
                rank += (v.y < yk) || (v.y == yk && (j + 1) < k);
                rank += (v.z < yk) || (v.z == yk && (j + 2) < k);
                rank += (v.w < yk) || (v.w == yk && (j + 3) < k);
            }
            g_ys[rank]   = yk;
            g_perm[rank] = k;
        }
    }
}

// ---------------------------------------------------------------------------
// Kernel 2: per-row loss (round-4 design, measured 9.5us)
// ---------------------------------------------------------------------------
__global__ void __launch_bounds__(N_TOT)
loss_kernel(const float* __restrict__ lw, const float* __restrict__ lm,
            float* __restrict__ out) {
    __shared__ float sLO[N_TOT];
    __shared__ float sY[N_TOT];
    __shared__ float sP[N_TOT + 1];
    __shared__ float warpS[16];

    int i = blockIdx.x;
    int k = threadIdx.x;
    int lane = k & 31, w = k >> 5;

    sLO[k] = g_LO[i * N_TOT + k];
    sY[k]  = g_ys[k];
    int pm = g_perm[k];
    float yi = lab(lw, lm, i);
    float yk = lab(lw, lm, k);
    __syncthreads();

    float e = (pm == i) ? 0.f : expf(sLO[pm]);

    float v = e;
    #pragma unroll
    for (int o = 1; o < 32; o <<= 1) {
        float nvl = __shfl_up_sync(0xffffffffu, v, o);
        if (lane >= o) v += nvl;
    }
    if (lane == 31) warpS[w] = v;
    __syncthreads();
    if (w == 0) {
        float s = (lane < 16) ? warpS[lane] : 0.f;
        #pragma unroll
        for (int o = 1; o < 16; o <<= 1) {
            float nvl = __shfl_up_sync(0xffffffffu, s, o);
            if (lane >= o) s += nvl;
        }
        if (lane < 16) warpS[lane] = s;
    }
    __syncthreads();
    float off = (w > 0) ? warpS[w - 1] : 0.f;
    float S = warpS[15];
    sP[k] = off + v - e;
    if (k == N_TOT - 1) sP[N_TOT] = off + v;
    __syncthreads();

    float t = fabsf(yi - yk);
    int lo_ = 0, hi_ = N_TOT;
    while (lo_ < hi_) { int mid = (lo_ + hi_) >> 1; if (sY[mid] >= yi) hi_ = mid; else lo_ = mid + 1; }
    int p = lo_;
    lo_ = 0; hi_ = p;
    while (lo_ < hi_) { int mid = (lo_ + hi_) >> 1; if (fabsf(yi - sY[mid]) < t) hi_ = mid; else lo_ = mid + 1; }
    int a = lo_;
    lo_ = p; hi_ = N_TOT;
    while (lo_ < hi_) { int mid = (lo_ + hi_) >> 1; if (fabsf(yi - sY[mid]) >= t) hi_ = mid; else lo_ = mid + 1; }
    int b = lo_;

    float denom = sP[a] + (S - sP[b]);
    float term = (k == i) ? 0.f : (sLO[k] - logf(denom));

    #pragma unroll
    for (int o = 16; o; o >>= 1) term += __shfl_xor_sync(0xffffffffu, term, o);
    __syncthreads();
    if (lane == 0) warpS[w] = term;
    __syncthreads();
    if (k == 0) {
        float s = 0.f;
        #pragma unroll
        for (int q = 0; q < 16; q++) s += warpS[q];
        atomicAdd(&g_acc, (double)s);
        __threadfence();
        int done = atomicAdd(&g_count, 1);
        if (done == N_TOT - 1) {
            double total = atomicAdd(&g_acc, 0.0);
            out[0] = (float)(-total / (double)(N_TOT * (N_TOT - 1)));
        }
    }
}

extern "C" void kernel_launch(void* const* d_in, const int* in_sizes, int n_in,
                              void* d_out, int out_size) {
    const float* wt = (const float*)d_in[0];
    const float* mt = (const float*)d_in[1];
    const float* lw = (const float*)d_in[2];
    const float* lm = (const float*)d_in[3];
    float* out = (float*)d_out;

    gemm_sort_kernel<<<65, 256>>>(wt, mt, lw, lm);
    loss_kernel<<<N_TOT, N_TOT>>>(lw, lm, out);
}

// round 7
// speedup vs baseline: 2.3867x; 1.2000x over previous
#include <cuda_runtime.h>
#include <cuda_bf16.h>
#include <math.h>
#include <stdint.h>

#define N_TOT 512
#define D_DIM 512

__device__ float  g_LO[N_TOT * N_TOT];   // lo = -dist/2, natural order
__device__ float  g_ys[N_TOT];           // labels sorted ascending
__device__ int    g_perm[N_TOT];         // g_ys[m] = y[g_perm[m]]
__device__ double g_acc;
__device__ int    g_count;

__device__ __forceinline__ const float* frow(const float* wt, const float* mt, int r) {
    return (r < 256) ? (wt + r * D_DIM) : (mt + (r - 256) * D_DIM);
}
__device__ __forceinline__ float lab(const float* lw, const float* lm, int r) {
    return (r < 256) ? lw[r] : lm[r - 256];
}

// ===================== warp-MMA helpers (HMMA bf16) =====================
__device__ __forceinline__ uint32_t smem_u32(const void* p) {
    uint32_t a;
    asm("{ .reg .u64 t; cvta.to.shared.u64 t, %1; cvt.u32.u64 %0, t; }" : "=r"(a) : "l"(p));
    return a;
}
__device__ __forceinline__ void ldsm4(uint32_t* r, uint32_t addr) {
    asm volatile("ldmatrix.sync.aligned.m8n8.x4.shared.b16 {%0,%1,%2,%3}, [%4];"
                 : "=r"(r[0]), "=r"(r[1]), "=r"(r[2]), "=r"(r[3]) : "r"(addr));
}
__device__ __forceinline__ void mma_bf16(float* c, const uint32_t* a, const uint32_t* b) {
    asm volatile("mma.sync.aligned.m16n8k16.row.col.f32.bf16.bf16.f32 "
                 "{%0,%1,%2,%3}, {%4,%5,%6,%7}, {%8,%9}, {%0,%1,%2,%3};"
                 : "+f"(c[0]), "+f"(c[1]), "+f"(c[2]), "+f"(c[3])
                 : "r"(a[0]), "r"(a[1]), "r"(a[2]), "r"(a[3]), "r"(b[0]), "r"(b[1]));
}

// bf16 split of 4 floats: hi = bf16(x), lo = bf16(x - hi)
__device__ __forceinline__ void split4(float4 f, uint2& h, uint2& l) {
    __nv_bfloat162 h0 = __floats2bfloat162_rn(f.x, f.y);
    __nv_bfloat162 h1 = __floats2bfloat162_rn(f.z, f.w);
    float2 g0 = __bfloat1622float2(h0), g1 = __bfloat1622float2(h1);
    __nv_bfloat162 l0 = __floats2bfloat162_rn(f.x - g0.x, f.y - g0.y);
    __nv_bfloat162 l1 = __floats2bfloat162_rn(f.z - g1.x, f.w - g1.y);
    h = make_uint2(*(uint32_t*)&h0, *(uint32_t*)&h1);
    l = make_uint2(*(uint32_t*)&l0, *(uint32_t*)&l1);
}

#define STRIDE 40          // bf16 elems per smem row (32 data + 8 pad)
#define BK 32
#define NCHUNK (D_DIM / BK)
#define NBUF 3

struct GemmSmem {
    float nA[64];
    float nB[32];
    unsigned short a_hi[NBUF][64 * STRIDE];
    unsigned short a_lo[NBUF][64 * STRIDE];
    unsigned short b_hi[NBUF][32 * STRIDE];
    unsigned short b_lo[NBUF][32 * STRIDE];
};

// ---------------------------------------------------------------------------
// Kernel 1: 128 HMMA GEMM blocks (64x32 tiles) + 4 sort blocks, 256 threads.
// ---------------------------------------------------------------------------
__global__ void __launch_bounds__(256, 1)
gemm_sort_kernel(const float* __restrict__ wt, const float* __restrict__ mt,
                 const float* __restrict__ lw, const float* __restrict__ lm) {
    __shared__ GemmSmem sm;

    const int t = threadIdx.x;
    const int bid = blockIdx.x;
    const int w = t >> 5, lane = t & 31;

    if (bid < 128) {
        const int i0 = (bid >> 4) * 64;
        const int j0 = (bid & 15) * 32;

        // load mapping: row group g = t>>3 (0..31), col f4 q = t&7
        const int g = t >> 3, q = t & 7;
        const float* arp0 = frow(wt, mt, i0 + g) + q * 4;
        const float* arp1 = frow(wt, mt, i0 + 32 + g) + q * 4;
        const float* brp  = frow(wt, mt, j0 + g) + q * 4;
        float na0 = 0.f, na1 = 0.f, nb = 0.f;

        const uint32_t a0e = g * STRIDE + q * 4;          // elem offset in a arrays
        const uint32_t a1e = (32 + g) * STRIDE + q * 4;
        const uint32_t b0e = g * STRIDE + q * 4;

        // warp tile: wm 0..3 (16 rows), wn 0..1 (16 cols)
        const int wm = w >> 1, wn = w & 1;
        float c[2][4] = {};

        const uint32_t a_hi_b = smem_u32(sm.a_hi[0]);
        const uint32_t a_lo_b = smem_u32(sm.a_lo[0]);
        const uint32_t b_hi_b = smem_u32(sm.b_hi[0]);
        const uint32_t b_lo_b = smem_u32(sm.b_lo[0]);
        const uint32_t astep = 64 * STRIDE * 2;
        const uint32_t bstep = 32 * STRIDE * 2;

        const uint32_t a_off = (uint32_t)((wm * 16 + (lane & 15)) * (STRIDE * 2) + ((lane >> 4) & 1) * 16);
        const uint32_t b_off = (uint32_t)((wn * 16 + (lane & 7) + ((lane >> 4) & 1) * 8) * (STRIDE * 2)
                                          + ((lane >> 3) & 1) * 16);

        float4 Ra0, Ra1, Rb;

        // ---- prologue: chunk 0 load+store, chunk 1 load ----
        Ra0 = *(const float4*)arp0; Ra1 = *(const float4*)arp1; Rb = *(const float4*)brp;
        {
            uint2 h, l;
            na0 += Ra0.x*Ra0.x + Ra0.y*Ra0.y + Ra0.z*Ra0.z + Ra0.w*Ra0.w;
            split4(Ra0, h, l);
            *(uint2*)&sm.a_hi[0][a0e] = h; *(uint2*)&sm.a_lo[0][a0e] = l;
            na1 += Ra1.x*Ra1.x + Ra1.y*Ra1.y + Ra1.z*Ra1.z + Ra1.w*Ra1.w;
            split4(Ra1, h, l);
            *(uint2*)&sm.a_hi[0][a1e] = h; *(uint2*)&sm.a_lo[0][a1e] = l;
            nb += Rb.x*Rb.x + Rb.y*Rb.y + Rb.z*Rb.z + Rb.w*Rb.w;
            split4(Rb, h, l);
            *(uint2*)&sm.b_hi[0][b0e] = h; *(uint2*)&sm.b_lo[0][b0e] = l;
        }
        Ra0 = *(const float4*)(arp0 + BK); Ra1 = *(const float4*)(arp1 + BK);
        Rb  = *(const float4*)(brp + BK);

        for (int n = 0; n < NCHUNK; n++) {
            const int cur = n % NBUF;
            if (n + 1 < NCHUNK) {
                const int nxt = (n + 1) % NBUF;
                uint2 h, l;
                na0 += Ra0.x*Ra0.x + Ra0.y*Ra0.y + Ra0.z*Ra0.z + Ra0.w*Ra0.w;
                split4(Ra0, h, l);
                *(uint2*)&sm.a_hi[nxt][a0e] = h; *(uint2*)&sm.a_lo[nxt][a0e] = l;
                na1 += Ra1.x*Ra1.x + Ra1.y*Ra1.y + Ra1.z*Ra1.z + Ra1.w*Ra1.w;
                split4(Ra1, h, l);
                *(uint2*)&sm.a_hi[nxt][a1e] = h; *(uint2*)&sm.a_lo[nxt][a1e] = l;
                nb += Rb.x*Rb.x + Rb.y*Rb.y + Rb.z*Rb.z + Rb.w*Rb.w;
                split4(Rb, h, l);
                *(uint2*)&sm.b_hi[nxt][b0e] = h; *(uint2*)&sm.b_lo[nxt][b0e] = l;
            }
            if (n + 2 < NCHUNK) {
                const int koff = (n + 2) * BK;
                Ra0 = *(const float4*)(arp0 + koff);
                Ra1 = *(const float4*)(arp1 + koff);
                Rb  = *(const float4*)(brp + koff);
            }
            __syncthreads();

            #pragma unroll
            for (int ks = 0; ks < 2; ks++) {
                const uint32_t ko = (uint32_t)(ks * 32);
                uint32_t Ah[4], Al[4], Bh[4], Bl[4];
                ldsm4(Ah, a_hi_b + cur * astep + a_off + ko);
                ldsm4(Al, a_lo_b + cur * astep + a_off + ko);
                ldsm4(Bh, b_hi_b + cur * bstep + b_off + ko);
                ldsm4(Bl, b_lo_b + cur * bstep + b_off + ko);
                mma_bf16(c[0], Ah, Bh + 0);
                mma_bf16(c[1], Ah, Bh + 2);
                mma_bf16(c[0], Ah, Bl + 0);
                mma_bf16(c[1], Ah, Bl + 2);
                mma_bf16(c[0], Al, Bh + 0);
                mma_bf16(c[1], Al, Bh + 2);
            }
        }

        // ---- norms: reduce over the 8 threads (q) sharing each row ----
        na0 += __shfl_xor_sync(0xffffffffu, na0, 1);
        na0 += __shfl_xor_sync(0xffffffffu, na0, 2);
        na0 += __shfl_xor_sync(0xffffffffu, na0, 4);
        na1 += __shfl_xor_sync(0xffffffffu, na1, 1);
        na1 += __shfl_xor_sync(0xffffffffu, na1, 2);
        na1 += __shfl_xor_sync(0xffffffffu, na1, 4);
        nb  += __shfl_xor_sync(0xffffffffu, nb, 1);
        nb  += __shfl_xor_sync(0xffffffffu, nb, 2);
        nb  += __shfl_xor_sync(0xffffffffu, nb, 4);
        __syncthreads();
        if (q == 0) { sm.nA[g] = na0; sm.nA[32 + g] = na1; sm.nB[g] = nb; }
        __syncthreads();

        // ---- epilogue ----
        const int r_lo = wm * 16 + (lane >> 2);
        const float ni0 = sm.nA[r_lo];
        const float ni1 = sm.nA[r_lo + 8];
        const int gi0 = i0 + r_lo;
        #pragma unroll
        for (int nf = 0; nf < 2; nf++) {
            const int colL = wn * 16 + nf * 8 + (lane & 3) * 2;
            const float nj0 = sm.nB[colL], nj1 = sm.nB[colL + 1];
            const int gcol = j0 + colL;
            float2 o0, o1;
            float sq;
            sq = fmaf(-2.f, c[nf][0], ni0 + nj0); o0.x = -0.5f * sqrtf(fmaxf(sq, 0.f));
            sq = fmaf(-2.f, c[nf][1], ni0 + nj1); o0.y = -0.5f * sqrtf(fmaxf(sq, 0.f));
            sq = fmaf(-2.f, c[nf][2], ni1 + nj0); o1.x = -0.5f * sqrtf(fmaxf(sq, 0.f));
            sq = fmaf(-2.f, c[nf][3], ni1 + nj1); o1.y = -0.5f * sqrtf(fmaxf(sq, 0.f));
            *(float2*)&g_LO[gi0 * N_TOT + gcol] = o0;
            *(float2*)&g_LO[(gi0 + 8) * N_TOT + gcol] = o1;
        }
    } else {
        // ---- 4 sort blocks: each ranks 128 labels (2 threads/element) ----
        const int sb = bid - 128;
        if (sb == 0 && t == 0) { g_acc = 0.0; g_count = 0; }
        float* ls = (float*)&sm;
        for (int m = t; m < N_TOT; m += 256) ls[m] = lab(lw, lm, m);
        __syncthreads();
        const int e = sb * 128 + (t >> 1);
        const int half = t & 1;
        const float ye = ls[e];
        int rank = 0;
        const float4* L4 = (const float4*)ls + half * 64;
        const int jbase = half * 256;
        #pragma unroll 4
        for (int j4 = 0; j4 < 64; j4++) {
            float4 v = L4[j4];
            int j = jbase + j4 * 4;
            rank += (v.x < ye) || (v.x == ye && (j + 0) < e);
            rank += (v.y < ye) || (v.y == ye && (j + 1) < e);
            rank += (v.z < ye) || (v.z == ye && (j + 2) < e);
            rank += (v.w < ye) || (v.w == ye && (j + 3) < e);
        }
        rank += __shfl_xor_sync(0xffffffffu, rank, 1);
        if (half == 0) { g_ys[rank] = ye; g_perm[rank] = e; }
    }
}

// ---------------------------------------------------------------------------
// Kernel 2: per-row loss. Precomputed sD, shared split point, fast exp/log.
// ---------------------------------------------------------------------------
__global__ void __launch_bounds__(N_TOT)
loss_kernel(const float* __restrict__ lw, const float* __restrict__ lm,
            float* __restrict__ out) {
    __shared__ float sLO[N_TOT];
    __shared__ float sY[N_TOT];
    __shared__ float sD[N_TOT];
    __shared__ float sP[N_TOT + 1];
    __shared__ float warpS[16];
    __shared__ int   sp;

    int i = blockIdx.x;
    int k = threadIdx.x;
    int lane = k & 31, w = k >> 5;

    sLO[k] = g_LO[i * N_TOT + k];
    sY[k]  = g_ys[k];
    int pm = g_perm[k];
    float yi = lab(lw, lm, i);
    float yk = lab(lw, lm, k);
    __syncthreads();

    sD[k] = fabsf(yi - sY[k]);
    if (k == 0) {
        int lo_ = 0, hi_ = N_TOT;
        while (lo_ < hi_) { int mid = (lo_ + hi_) >> 1; if (sY[mid] >= yi) hi_ = mid; else lo_ = mid + 1; }
        sp = lo_;
    }

    // e in sorted order, diagonal forced to 0
    float e = (pm == i) ? 0.f : __expf(sLO[pm]);

    // exclusive prefix sum of e
    float v = e;
    #pragma unroll
    for (int o = 1; o < 32; o <<= 1) {
        float nvl = __shfl_up_sync(0xffffffffu, v, o);
        if (lane >= o) v += nvl;
    }
    if (lane == 31) warpS[w] = v;
    __syncthreads();
    if (w == 0) {
        float s = (lane < 16) ? warpS[lane] : 0.f;
        #pragma unroll
        for (int o = 1; o < 16; o <<= 1) {
            float nvl = __shfl_up_sync(0xffffffffu, s, o);
            if (lane >= o) s += nvl;
        }
        if (lane < 16) warpS[lane] = s;
    }
    __syncthreads();
    float off = (w > 0) ? warpS[w - 1] : 0.f;
    float S = warpS[15];
    sP[k] = off + v - e;
    if (k == N_TOT - 1) sP[N_TOT] = off + v;
    __syncthreads();

    const int p = sp;
    float t = fabsf(yi - yk);
    // a = first m in [0,p) with sD[m] < t   (sD decreasing there)
    int lo_ = 0, hi_ = p;
    while (lo_ < hi_) { int mid = (lo_ + hi_) >> 1; if (sD[mid] < t) hi_ = mid; else lo_ = mid + 1; }
    int a = lo_;
    // b = first m in [p,n) with sD[m] >= t  (sD increasing there)
    lo_ = p; hi_ = N_TOT;
    while (lo_ < hi_) { int mid = (lo_ + hi_) >> 1; if (sD[mid] >= t) hi_ = mid; else lo_ = mid + 1; }
    int b = lo_;

    float denom = sP[a] + (S - sP[b]);
    float term = (k == i) ? 0.f : (sLO[k] - __logf(denom));

    #pragma unroll
    for (int o = 16; o; o >>= 1) term += __shfl_xor_sync(0xffffffffu, term, o);
    __syncthreads();
    if (lane == 0) warpS[w] = term;
    __syncthreads();
    if (k == 0) {
        float s = 0.f;
        #pragma unroll
        for (int qq = 0; qq < 16; qq++) s += warpS[qq];
        atomicAdd(&g_acc, (double)s);
        __threadfence();
        int done = atomicAdd(&g_count, 1);
        if (done == N_TOT - 1) {
            double total = atomicAdd(&g_acc, 0.0);
            out[0] = (float)(-total / (double)(N_TOT * (N_TOT - 1)));
        }
    }
}

extern "C" void kernel_launch(void* const* d_in, const int* in_sizes, int n_in,
                              void* d_out, int out_size) {
    const float* wt = (const float*)d_in[0];
    const float* mt = (const float*)d_in[1];
    const float* lw = (const float*)d_in[2];
    const float* lm = (const float*)d_in[3];
    float* out = (float*)d_out;

    gemm_sort_kernel<<<132, 256>>>(wt, mt, lw, lm);
    loss_kernel<<<N_TOT, N_TOT>>>(lw, lm, out);
}

// round 8
// speedup vs baseline: 2.4605x; 1.0309x over previous
#include <cuda_runtime.h>
#include <cuda_bf16.h>
#include <math.h>
#include <stdint.h>

#define N_TOT 512
#define D_DIM 512

__device__ float  g_LO[N_TOT * N_TOT];   // lo = -dist/2, natural order
__device__ float  g_ys[N_TOT];           // labels sorted ascending
__device__ int    g_perm[N_TOT];         // g_ys[m] = y[g_perm[m]]
__device__ double g_acc;
__device__ int    g_count;

__device__ __forceinline__ const float* frow(const float* wt, const float* mt, int r) {
    return (r < 256) ? (wt + r * D_DIM) : (mt + (r - 256) * D_DIM);
}
__device__ __forceinline__ float lab(const float* lw, const float* lm, int r) {
    return (r < 256) ? lw[r] : lm[r - 256];
}

// ===================== warp-MMA helpers (HMMA bf16) =====================
__device__ __forceinline__ uint32_t smem_u32(const void* p) {
    uint32_t a;
    asm("{ .reg .u64 t; cvta.to.shared.u64 t, %1; cvt.u32.u64 %0, t; }" : "=r"(a) : "l"(p));
    return a;
}
__device__ __forceinline__ void ldsm4(uint32_t* r, uint32_t addr) {
    asm volatile("ldmatrix.sync.aligned.m8n8.x4.shared.b16 {%0,%1,%2,%3}, [%4];"
                 : "=r"(r[0]), "=r"(r[1]), "=r"(r[2]), "=r"(r[3]) : "r"(addr));
}
__device__ __forceinline__ void mma_bf16(float* c, const uint32_t* a, const uint32_t* b) {
    asm volatile("mma.sync.aligned.m16n8k16.row.col.f32.bf16.bf16.f32 "
                 "{%0,%1,%2,%3}, {%4,%5,%6,%7}, {%8,%9}, {%0,%1,%2,%3};"
                 : "+f"(c[0]), "+f"(c[1]), "+f"(c[2]), "+f"(c[3])
                 : "r"(a[0]), "r"(a[1]), "r"(a[2]), "r"(a[3]), "r"(b[0]), "r"(b[1]));
}

// bf16 split of 4 floats: hi = bf16(x), lo = bf16(x - hi)
__device__ __forceinline__ void split4(float4 f, uint2& h, uint2& l) {
    __nv_bfloat162 h0 = __floats2bfloat162_rn(f.x, f.y);
    __nv_bfloat162 h1 = __floats2bfloat162_rn(f.z, f.w);
    float2 g0 = __bfloat1622float2(h0), g1 = __bfloat1622float2(h1);
    __nv_bfloat162 l0 = __floats2bfloat162_rn(f.x - g0.x, f.y - g0.y);
    __nv_bfloat162 l1 = __floats2bfloat162_rn(f.z - g1.x, f.w - g1.y);
    h = make_uint2(*(uint32_t*)&h0, *(uint32_t*)&h1);
    l = make_uint2(*(uint32_t*)&l0, *(uint32_t*)&l1);
}

#define STRIDE 40          // bf16 elems per smem row (32 data + 8 pad)
#define BK 32
#define NCHUNK (D_DIM / BK)
#define NBUF 3
#define NTILES 136         // 16*17/2 upper-triangle 32x32 tiles
#define GRID_G (NTILES + 4)

struct GemmSmem {
    float nA[32];
    float nB[32];
    union {
        struct {
            unsigned short a_hi[NBUF][32 * STRIDE];
            unsigned short a_lo[NBUF][32 * STRIDE];
            unsigned short b_hi[NBUF][32 * STRIDE];
            unsigned short b_lo[NBUF][32 * STRIDE];
        } buf;
        float stage[32][33];
    } u;
};

// ---------------------------------------------------------------------------
// Kernel 1: 136 HMMA GEMM blocks (upper-triangle 32x32 tiles, mirror write)
//           + 4 sort blocks. 256 threads.
// ---------------------------------------------------------------------------
__global__ void __launch_bounds__(256)
gemm_sort_kernel(const float* __restrict__ wt, const float* __restrict__ mt,
                 const float* __restrict__ lw, const float* __restrict__ lm) {
    __shared__ GemmSmem sm;

    const int t = threadIdx.x;
    const int bid = blockIdx.x;
    const int w = t >> 5, lane = t & 31;

    if (bid < NTILES) {
        // triangular decode: (ti, tj) with ti <= tj over 16x16 tile grid
        int ti = 0, base = 0;
        while (base + (16 - ti) <= bid) { base += 16 - ti; ti++; }
        const int tj = ti + (bid - base);
        const int I = ti * 32, J = tj * 32;

        const int g = t >> 3, q = t & 7;     // row group, float4 col
        const float* arp = frow(wt, mt, I + g) + q * 4;
        const float* brp = frow(wt, mt, J + g) + q * 4;
        float na = 0.f, nb = 0.f;
        const uint32_t se = g * STRIDE + q * 4;

        // warp tile: wm 0..1 (16 rows), wn 0..3 (8 cols)
        const int wm = w >> 2, wn = w & 3;
        float c[4] = {};

        const uint32_t a_hi_b = smem_u32(sm.u.buf.a_hi[0]);
        const uint32_t a_lo_b = smem_u32(sm.u.buf.a_lo[0]);
        const uint32_t b_hi_b = smem_u32(sm.u.buf.b_hi[0]);
        const uint32_t b_lo_b = smem_u32(sm.u.buf.b_lo[0]);
        const uint32_t step = 32 * STRIDE * 2;

        const uint32_t a_off = (uint32_t)((wm * 16 + (lane & 15)) * (STRIDE * 2) + ((lane >> 4) & 1) * 16);
        const uint32_t b_off = (uint32_t)((wn * 8 + (lane & 7)) * (STRIDE * 2) + (lane >> 3) * 16);

        float4 Ra, Rb;
        // prologue: chunk0 load+store, chunk1 prefetch
        Ra = *(const float4*)arp; Rb = *(const float4*)brp;
        {
            uint2 h, l;
            na += Ra.x*Ra.x + Ra.y*Ra.y + Ra.z*Ra.z + Ra.w*Ra.w;
            split4(Ra, h, l);
            *(uint2*)&sm.u.buf.a_hi[0][se] = h; *(uint2*)&sm.u.buf.a_lo[0][se] = l;
            nb += Rb.x*Rb.x + Rb.y*Rb.y + Rb.z*Rb.z + Rb.w*Rb.w;
            split4(Rb, h, l);
            *(uint2*)&sm.u.buf.b_hi[0][se] = h; *(uint2*)&sm.u.buf.b_lo[0][se] = l;
        }
        Ra = *(const float4*)(arp + BK); Rb = *(const float4*)(brp + BK);

        for (int n = 0; n < NCHUNK; n++) {
            const int cur = n % NBUF;
            if (n + 1 < NCHUNK) {
                const int nxt = (n + 1) % NBUF;
                uint2 h, l;
                na += Ra.x*Ra.x + Ra.y*Ra.y + Ra.z*Ra.z + Ra.w*Ra.w;
                split4(Ra, h, l);
                *(uint2*)&sm.u.buf.a_hi[nxt][se] = h; *(uint2*)&sm.u.buf.a_lo[nxt][se] = l;
                nb += Rb.x*Rb.x + Rb.y*Rb.y + Rb.z*Rb.z + Rb.w*Rb.w;
                split4(Rb, h, l);
                *(uint2*)&sm.u.buf.b_hi[nxt][se] = h; *(uint2*)&sm.u.buf.b_lo[nxt][se] = l;
            }
            if (n + 2 < NCHUNK) {
                const int ko = (n + 2) * BK;
                Ra = *(const float4*)(arp + ko);
                Rb = *(const float4*)(brp + ko);
            }
            __syncthreads();

            // B: one ldsm4 covers all 32 k (4 k8 chunks)
            uint32_t Bh[4], Bl[4];
            ldsm4(Bh, b_hi_b + cur * step + b_off);
            ldsm4(Bl, b_lo_b + cur * step + b_off);
            #pragma unroll
            for (int ks = 0; ks < 2; ks++) {
                uint32_t Ah[4], Al[4];
                ldsm4(Ah, a_hi_b + cur * step + a_off + ks * 32);
                ldsm4(Al, a_lo_b + cur * step + a_off + ks * 32);
                mma_bf16(c, Ah, Bh + ks * 2);
                mma_bf16(c, Ah, Bl + ks * 2);
                mma_bf16(c, Al, Bh + ks * 2);
            }
        }

        // norms: reduce across the 8 threads (q) of each row
        na += __shfl_xor_sync(0xffffffffu, na, 1);
        na += __shfl_xor_sync(0xffffffffu, na, 2);
        na += __shfl_xor_sync(0xffffffffu, na, 4);
        nb += __shfl_xor_sync(0xffffffffu, nb, 1);
        nb += __shfl_xor_sync(0xffffffffu, nb, 2);
        nb += __shfl_xor_sync(0xffffffffu, nb, 4);
        __syncthreads();                        // all ldsm reads done -> stage reuse safe
        if (q == 0) { sm.nA[g] = na; sm.nB[g] = nb; }
        __syncthreads();

        // epilogue: direct write + stage for mirror
        const int r0 = wm * 16 + (lane >> 2);
        const int cL = wn * 8 + (lane & 3) * 2;
        const float ni0 = sm.nA[r0], ni1 = sm.nA[r0 + 8];
        const float nj0 = sm.nB[cL], nj1 = sm.nB[cL + 1];
        float sq, v00, v01, v10, v11;
        sq = fmaf(-2.f, c[0], ni0 + nj0); v00 = -0.5f * sqrtf(fmaxf(sq, 0.f));
        sq = fmaf(-2.f, c[1], ni0 + nj1); v01 = -0.5f * sqrtf(fmaxf(sq, 0.f));
        sq = fmaf(-2.f, c[2], ni1 + nj0); v10 = -0.5f * sqrtf(fmaxf(sq, 0.f));
        sq = fmaf(-2.f, c[3], ni1 + nj1); v11 = -0.5f * sqrtf(fmaxf(sq, 0.f));
        *(float2*)&g_LO[(I + r0) * N_TOT + J + cL]     = make_float2(v00, v01);
        *(float2*)&g_LO[(I + r0 + 8) * N_TOT + J + cL] = make_float2(v10, v11);

        if (ti != tj) {
            sm.u.stage[r0][cL] = v00;     sm.u.stage[r0][cL + 1] = v01;
            sm.u.stage[r0 + 8][cL] = v10; sm.u.stage[r0 + 8][cL + 1] = v11;
            __syncthreads();
            const int mc = t >> 3;            // mirror row (0..31)
            const int rg = (t & 7) * 4;       // 4 source rows
            float4 o;
            o.x = sm.u.stage[rg + 0][mc];
            o.y = sm.u.stage[rg + 1][mc];
            o.z = sm.u.stage[rg + 2][mc];
            o.w = sm.u.stage[rg + 3][mc];
            *(float4*)&g_LO[(J + mc) * N_TOT + I + rg] = o;
        }
    } else {
        // ---- 4 sort blocks: each ranks 128 labels (2 threads/element) ----
        const int sb = bid - NTILES;
        if (sb == 0 && t == 0) { g_acc = 0.0; g_count = 0; }
        float* ls = (float*)&sm;
        for (int m = t; m < N_TOT; m += 256) ls[m] = lab(lw, lm, m);
        __syncthreads();
        const int e = sb * 128 + (t >> 1);
        const int half = t & 1;
        const float ye = ls[e];
        int rank = 0;
        const float4* L4 = (const float4*)ls + half * 64;
        const int jbase = half * 256;
        #pragma unroll 4
        for (int j4 = 0; j4 < 64; j4++) {
            float4 v = L4[j4];
            int j = jbase + j4 * 4;
            rank += (v.x < ye) || (v.x == ye && (j + 0) < e);
            rank += (v.y < ye) || (v.y == ye && (j + 1) < e);
            rank += (v.z < ye) || (v.z == ye && (j + 2) < e);
            rank += (v.w < ye) || (v.w == ye && (j + 3) < e);
        }
        rank += __shfl_xor_sync(0xffffffffu, rank, 1);
        if (half == 0) { g_ys[rank] = ye; g_perm[rank] = e; }
    }
}

// ---------------------------------------------------------------------------
// Kernel 2: per-row loss, sorted domain. Thread = sorted position m.
// Own-side boundary = adjacency (+tie extension); other side = 1 binary search.
// ---------------------------------------------------------------------------
__global__ void __launch_bounds__(N_TOT)
loss_kernel(const float* __restrict__ lw, const float* __restrict__ lm,
            float* __restrict__ out) {
    __shared__ float sLO[N_TOT];
    __shared__ float sY[N_TOT];
    __shared__ float sD[N_TOT];
    __shared__ float sP[N_TOT + 1];
    __shared__ float warpS[16];
    __shared__ int   sp, spos;

    const int i = blockIdx.x;
    const int m = threadIdx.x;
    const int lane = m & 31, w = m >> 5;

    sLO[m] = g_LO[i * N_TOT + m];
    sY[m]  = g_ys[m];
    const int pm = g_perm[m];
    const float yi = lab(lw, lm, i);
    if (pm == i) spos = m;
    __syncthreads();

    const float tm = fabsf(yi - sY[m]);
    sD[m] = tm;
    if (m == 0) {
        int lo_ = 0, hi_ = N_TOT;
        while (lo_ < hi_) { int mid = (lo_ + hi_) >> 1; if (sY[mid] >= yi) hi_ = mid; else lo_ = mid + 1; }
        sp = lo_;
    }

    // e and lo in sorted order (diagonal e -> 0)
    const float lo_s = sLO[pm];
    const float e = (pm == i) ? 0.f : __expf(lo_s);

    // exclusive prefix sum of e
    float v = e;
    #pragma unroll
    for (int o = 1; o < 32; o <<= 1) {
        float nvl = __shfl_up_sync(0xffffffffu, v, o);
        if (lane >= o) v += nvl;
    }
    if (lane == 31) warpS[w] = v;
    __syncthreads();
    if (w == 0) {
        float s = (lane < 16) ? warpS[lane] : 0.f;
        #pragma unroll
        for (int o = 1; o < 16; o <<= 1) {
            float nvl = __shfl_up_sync(0xffffffffu, s, o);
            if (lane >= o) s += nvl;
        }
        if (lane < 16) warpS[lane] = s;
    }
    __syncthreads();
    const float off = (w > 0) ? warpS[w - 1] : 0.f;
    const float S = warpS[15];
    sP[m] = off + v - e;
    if (m == N_TOT - 1) sP[N_TOT] = off + v;
    __syncthreads();

    const int p = sp;
    int a, b;
    if (m < p) {
        // own side L [0,p): sD decreasing. a = first j with sD[j] < tm.
        int j = m + 1;
        while (j < p && sD[j] == tm) j++;
        a = j;
        // other side R [p,n): increasing. b = first j with sD[j] >= tm.
        int lo_ = p, hi_ = N_TOT;
        while (lo_ < hi_) { int mid = (lo_ + hi_) >> 1; if (sD[mid] >= tm) hi_ = mid; else lo_ = mid + 1; }
        b = lo_;
    } else {
        // own side R: b = first j with sD[j] >= tm (walk back over ties).
        int j = m;
        while (j > p && sD[j - 1] == tm) j--;
        b = j;
        // other side L [0,p): decreasing. a = first j with sD[j] < tm.
        int lo_ = 0, hi_ = p;
        while (lo_ < hi_) { int mid = (lo_ + hi_) >> 1; if (sD[mid] < tm) hi_ = mid; else lo_ = mid + 1; }
        a = lo_;
    }

    const float denom = sP[a] + (S - sP[b]);
    float term = (m == spos) ? 0.f : (lo_s - __logf(denom));

    #pragma unroll
    for (int o = 16; o; o >>= 1) term += __shfl_xor_sync(0xffffffffu, term, o);
    __syncthreads();
    if (lane == 0) warpS[w] = term;
    __syncthreads();
    if (m == 0) {
        float s = 0.f;
        #pragma unroll
        for (int qq = 0; qq < 16; qq++) s += warpS[qq];
        atomicAdd(&g_acc, (double)s);
        __threadfence();
        int done = atomicAdd(&g_count, 1);
        if (done == N_TOT - 1) {
            double total = atomicAdd(&g_acc, 0.0);
            out[0] = (float)(-total / (double)(N_TOT * (N_TOT - 1)));
        }
    }
}

extern "C" void kernel_launch(void* const* d_in, const int* in_sizes, int n_in,
                              void* d_out, int out_size) {
    const float* wt = (const float*)d_in[0];
    const float* mt = (const float*)d_in[1];
    const float* lw = (const float*)d_in[2];
    const float* lm = (const float*)d_in[3];
    float* out = (float*)d_out;

    gemm_sort_kernel<<<GRID_G, 256>>>(wt, mt, lw, lm);
    loss_kernel<<<N_TOT, N_TOT>>>(lw, lm, out);
}